// round 15
// baseline (speedup 1.0000x reference)
#include <cuda_runtime.h>
#include <stdint.h>

// Problem shape (fixed per reference)
#define BB 256
#define NN 1024
#define LL 128
#define MM 512
#define RPW 4                 // rows per warp
#define ROWS_PER_BLK 32       // 8 warps * 4 rows; always within one batch
#define TILES ((BB * NN) / ROWS_PER_BLK)   // 8192
#define GRID 1184             // 148 SMs * 8 resident 256-thread blocks

// Grid-stride version of the champion kernel: identical per-tile body
// (32-row tile, block-local 32-bit flag mask, float4 MLP-4 payload,
// streaming .cs loads/stores), but 1184 blocks loop over the 8192 tiles.
// Double-buffered mask keeps it at two barriers per tile.
__global__ void __launch_bounds__(256)
fused_kernel(const float4* __restrict__ in, float4* __restrict__ out,
             const void* __restrict__ idx) {
    __shared__ unsigned int s_mask[2];

    int tid  = threadIdx.x;
    int lane = tid & 31;
    int warp = tid >> 5;

    // ---- dtype probe (per warp, same cached 128 B) ----
    // True int64: first 16 values all in [0, NN). int32-read-as-int64:
    // value = lo + hi*2^32, out of range unless hi==0 (P ~ (1/1024)^16 ~ 0).
    long long pv = 0;
    if (lane < 16) pv = ((const long long*)idx)[lane];
    int ok = (pv >= 0 && pv < NN);
    unsigned ballot = __ballot_sync(0xffffffffu, ok);
    int is64 = ((ballot & 0xFFFFu) == 0xFFFFu);

    if (tid < 2) s_mask[tid] = 0u;
    // (ordered before first atomicOr by the in-loop barrier below)

    const float inv = 1.0f / (float)(LL - 1);
    int base = lane * 4;
    int sh = warp * RPW;
    int buf = 0;

    __syncthreads();

    for (int t = blockIdx.x; t < TILES; t += GRID) {
        int row_lo = t * ROWS_PER_BLK;
        int b = row_lo >> 10;
        int local_lo = row_lo & (NN - 1);

        // ---- scan this batch's 512 indices (1 vector load per thread) ----
        {
            int n0, n1;
            if (is64) {
                longlong2 v2 = ((const longlong2*)idx)[b * (MM / 2) + tid];
                n0 = (int)v2.x; n1 = (int)v2.y;
            } else {
                int2 v2 = ((const int2*)idx)[b * (MM / 2) + tid];
                n0 = v2.x; n1 = v2.y;
            }
            unsigned d0 = (unsigned)(n0 - local_lo);
            unsigned d1 = (unsigned)(n1 - local_lo);
            if (d0 < (unsigned)ROWS_PER_BLK) atomicOr(&s_mask[buf], 1u << d0);
            if (d1 < (unsigned)ROWS_PER_BLK) atomicOr(&s_mask[buf], 1u << d1);
        }
        __syncthreads();                       // mask complete
        unsigned word = s_mask[buf];
        __syncthreads();                       // all readers done
        if (tid == 0) s_mask[buf] = 0u;        // recycle (next use 2 iters away)

        int row0 = row_lo + warp * RPW;

        bool m[RPW];
        #pragma unroll
        for (int r = 0; r < RPW; r++) m[r] = (word >> (sh + r)) & 1u;

        float4 v[RPW];
        float sv[RPW], ev[RPW];

        // ---- Phase 1: front-batched loads (MLP ~= 4) ----
        #pragma unroll
        for (int r = 0; r < RPW; r++) {
            const float* srow = (const float*)(in + (size_t)(row0 + r) * 32);
            if (!m[r]) {
                v[r] = __ldcs((const float4*)srow + lane);
            } else {
                float a = 0.f, e = 0.f;
                if (lane == 0)  a = __ldcs(&srow[0]);
                if (lane == 31) e = __ldcs(&srow[LL - 1]);
                sv[r] = a; ev[r] = e;
            }
        }

        // ---- Phase 2: linspace for flagged rows ----
        #pragma unroll
        for (int r = 0; r < RPW; r++) {
            if (m[r]) {
                float start = __shfl_sync(0xffffffffu, sv[r], 0);
                float end   = __shfl_sync(0xffffffffu, ev[r], 31);
                float delta = end - start;
                v[r].x = start + delta * ((float)(base + 0) * inv);
                v[r].y = start + delta * ((float)(base + 1) * inv);
                v[r].z = start + delta * ((float)(base + 2) * inv);
                v[r].w = start + delta * ((float)(base + 3) * inv);
            }
        }

        // ---- Phase 3: streaming stores ----
        #pragma unroll
        for (int r = 0; r < RPW; r++) {
            __stcs(out + (size_t)(row0 + r) * 32 + lane, v[r]);
        }

        buf ^= 1;
    }
}

extern "C" void kernel_launch(void* const* d_in, const int* in_sizes, int n_in,
                              void* d_out, int out_size) {
    const float* patches = (const float*)d_in[0];
    const void*  midx    = d_in[1];
    float*       out     = (float*)d_out;

    fused_kernel<<<GRID, 256>>>((const float4*)patches, (float4*)out, midx);
}

// round 16
// speedup vs baseline: 1.0499x; 1.0499x over previous
#include <cuda_runtime.h>
#include <stdint.h>

// Problem shape (fixed per reference)
#define BB 256
#define NN 1024
#define LL 128
#define MM 512
#define RPW 4              // rows per warp
#define ROWS_PER_BLK 32    // 8 warps * 4 rows; always within one batch

// ============================================================================
// FINAL (champion R6 config, best measured: 41.31 us total / 34.37 us kernel,
// DRAM ~68% of peak — the mixed 128MB-write / 88MB-read stream wall).
//
// Single fused kernel: each 256-thread block covers 32 consecutive rows of
// one batch. It scans that batch's 512 masked-indices to build a 32-bit
// block-local flag word (indices are 97% L2-resident: 32 blocks/batch share
// 4 KB), then writes its 32 rows exactly once:
//   - unflagged row: float4 streaming copy (coalesced, .cs evict-first)
//   - flagged row:   read ONLY elements 0 and 127, generate
//                    linspace(row[0], row[127], 128) in registers
// Payload loads are front-batched across the warp's 4 rows -> MLP ~= 4.
//
// Swept and rejected: 64-row masks, persistent blocks + prefetch pipeline,
// warp-autonomous scans, L2 evict_last policy, 256-bit v8 ld/st, grid-stride
// loops — all within noise or worse (register pressure / occupancy trade).
// ============================================================================
__global__ void __launch_bounds__(256)
fused_kernel(const float4* __restrict__ in, float4* __restrict__ out,
             const void* __restrict__ idx) {
    __shared__ unsigned int s_mask;

    int tid  = threadIdx.x;
    int lane = tid & 31;
    int warp = tid >> 5;
    int row_lo = blockIdx.x * ROWS_PER_BLK;    // block's first GLOBAL row
    int b = row_lo >> 10;                       // batch = row / NN
    int local_lo = row_lo & (NN - 1);           // block's first LOCAL row

    // ---- dtype probe (per warp, same cached 128 B) ----
    // True int64: first 16 values all in [0, NN). int32-read-as-int64:
    // value = lo + hi*2^32, out of range unless hi==0 (P ~ (1/1024)^16 ~ 0).
    long long pv = 0;
    if (lane < 16) pv = ((const long long*)idx)[lane];
    int ok = (pv >= 0 && pv < NN);
    unsigned ballot = __ballot_sync(0xffffffffu, ok);
    int is64 = ((ballot & 0xFFFFu) == 0xFFFFu);

    if (tid == 0) s_mask = 0u;
    __syncthreads();

    // ---- scan this batch's 512 indices; flag hits in [local_lo, +32) ----
    #pragma unroll
    for (int k = 0; k < MM / 256; k++) {        // 2 indices per thread
        int j = b * MM + tid + k * 256;
        int n = is64 ? (int)((const long long*)idx)[j]
                     : ((const int*)idx)[j];
        unsigned d = (unsigned)(n - local_lo);  // batch-LOCAL comparison
        if (d < (unsigned)ROWS_PER_BLK) atomicOr(&s_mask, 1u << d);
    }
    __syncthreads();

    unsigned word = s_mask;
    int row0 = row_lo + warp * RPW;
    int sh = warp * RPW;

    bool m[RPW];
    #pragma unroll
    for (int r = 0; r < RPW; r++) m[r] = (word >> (sh + r)) & 1u;

    float4 v[RPW];
    float sv[RPW], ev[RPW];

    // ---- Phase 1: front-batched loads (MLP ~= 4) ----
    #pragma unroll
    for (int r = 0; r < RPW; r++) {
        const float* srow = (const float*)(in + (size_t)(row0 + r) * 32);
        if (!m[r]) {
            v[r] = __ldcs((const float4*)srow + lane);
        } else {
            float a = 0.f, e = 0.f;
            if (lane == 0)  a = __ldcs(&srow[0]);
            if (lane == 31) e = __ldcs(&srow[LL - 1]);
            sv[r] = a; ev[r] = e;
        }
    }

    // ---- Phase 2: linspace for flagged rows ----
    const float inv = 1.0f / (float)(LL - 1);
    int base = lane * 4;
    #pragma unroll
    for (int r = 0; r < RPW; r++) {
        if (m[r]) {
            float start = __shfl_sync(0xffffffffu, sv[r], 0);
            float end   = __shfl_sync(0xffffffffu, ev[r], 31);
            float delta = end - start;
            v[r].x = start + delta * ((float)(base + 0) * inv);
            v[r].y = start + delta * ((float)(base + 1) * inv);
            v[r].z = start + delta * ((float)(base + 2) * inv);
            v[r].w = start + delta * ((float)(base + 3) * inv);
        }
    }

    // ---- Phase 3: streaming stores ----
    #pragma unroll
    for (int r = 0; r < RPW; r++) {
        __stcs(out + (size_t)(row0 + r) * 32 + lane, v[r]);
    }
}

extern "C" void kernel_launch(void* const* d_in, const int* in_sizes, int n_in,
                              void* d_out, int out_size) {
    const float* patches = (const float*)d_in[0];
    const void*  midx    = d_in[1];
    float*       out     = (float*)d_out;

    int blocks = (BB * NN) / ROWS_PER_BLK;   // 8192
    fused_kernel<<<blocks, 256>>>((const float4*)patches, (float4*)out, midx);
}